// round 17
// baseline (speedup 1.0000x reference)
#include <cuda_runtime.h>
#include <cstdint>

#define B_    256
#define T_    1000
#define F_    64
#define H1_   256
#define H2_   128
#define NCLS_ 5
#define DMLP_ 128

#define GCOL  16      // column groups (hidden-unit split)
#define GB    8       // batch groups
#define BC    32      // batch rows per batch group (256/8)
#define U1    16      // layer-1 hidden units per column group
#define U2    8       // layer-2 hidden units per column group
#define NTHR  256

// padded SMEM strides (floats): stride*4 ≡ 16 mod 128 → bank offset 4 per row
#define H1P   260
#define H2P   132
#define FP_   68

// ---- global exchange state ----
__device__ float g_h1buf[2][B_][H1_];   // slot t&1 holds h1(t)
__device__ float g_h2buf[2][B_][H2_];   // slot t&1 holds h2(t-1)
__device__ int   g_cnt1[GB];            // bumped after layer-1 store (h1(t) published)
__device__ int   g_cnt2[GB];            // bumped after layer-2 store (h2(t-1) published)

// ---- SMEM (~186 KB) ----
// Weights in dot-product layout: [k2][unit][p] where p=0 -> {Wi[2k2],Wi[2k2+1],Wf[2k2],Wf[2k2+1]},
// p=1 -> same for g,o. Each [k2][u][p] is one 16B ulonglong2 (two f32x2 gate-pairs).
struct SmemLayout {
    ulonglong2 Wh1d[H1_/2][U1][2];   // 64 KB
    ulonglong2 Wx1d[F_/2][U1][2];    // 16 KB
    ulonglong2 W2ad[H1_/2][U2][2];   // 32 KB
    ulonglong2 W2bd[H2_/2][U2][2];   // 16 KB
    float h1s[BC][H1P];              // staged h1(t-1)  32.5 KB
    float h2s[BC][H2P];              // staged h2(t-2)  16.5 KB
    float xs[BC][FP_];               // staged x_t       8.5 KB
    float bias1[U1 * 4];
    float bias2[U2 * 4];
};
#define SMEM_BYTES (sizeof(SmemLayout))

// ---- packed fp32x2 helpers ----
__device__ __forceinline__ unsigned long long pack2(float a, float b) {
    unsigned long long r;
    asm("mov.b64 %0, {%1, %2};" : "=l"(r) : "f"(a), "f"(b));
    return r;
}
__device__ __forceinline__ float2 unpack2(unsigned long long v) {
    float2 r;
    asm("mov.b64 {%0, %1}, %2;" : "=f"(r.x), "=f"(r.y) : "l"(v));
    return r;
}
#define FMA2(acc, a, b) \
    asm("fma.rn.f32x2 %0, %1, %2, %0;" : "+l"(acc) : "l"(a), "l"(b))

__device__ __forceinline__ float sigf(float v) {
    return 1.0f / (1.0f + __expf(-v));
}
__device__ __forceinline__ float tanh_f(float v) {
    v = fminf(fmaxf(v, -15.0f), 15.0f);
    float e = __expf(-2.0f * v);
    return (1.0f - e) / (1.0f + e);
}

// ---- init: zero initial state + counters (runs every graph replay) ----
__global__ void lstm_init_kernel() {
    int i = blockIdx.x * blockDim.x + threadIdx.x;
    int stride = gridDim.x * blockDim.x;
    if (i < GB) { g_cnt1[i] = 0; g_cnt2[i] = 0; }
    for (int j = i; j < B_ * H1_; j += stride) ((float*)g_h1buf)[j] = 0.0f;  // slot 0
    for (int j = i; j < B_ * H2_; j += stride) ((float*)g_h2buf)[j] = 0.0f;  // slot 0
}

// ---- persistent two-layer LSTM ----
extern "C" __global__ void __launch_bounds__(NTHR, 1)
lstm_persistent(const float* __restrict__ x,
                const float* __restrict__ Wih1, const float* __restrict__ Whh1,
                const float* __restrict__ bih1, const float* __restrict__ bhh1,
                const float* __restrict__ Wih2, const float* __restrict__ Whh2,
                const float* __restrict__ bih2, const float* __restrict__ bhh2)
{
    extern __shared__ float smem_raw[];
    SmemLayout* S = (SmemLayout*)smem_raw;

    const int tid = threadIdx.x;
    const int cg  = blockIdx.x & (GCOL - 1);
    const int bg  = blockIdx.x >> 4;
    const int B0  = bg * BC;
    const int u0  = cg * U1;
    const int v0  = cg * U2;

    // ---- one-time weight transpose into dot-product layout ----
    {
        float* W = (float*)S->Wh1d;                       // 16384 floats
        for (int idx = tid; idx < H1_ * U1 * 4; idx += NTHR) {
            int k2 = idx >> 7, rem = idx & 127;
            int u = rem >> 3, p = (rem >> 2) & 1, j = rem & 3;
            int gate = 2 * p + (j >> 1), kk = 2 * k2 + (j & 1);
            W[idx] = Whh1[(gate * H1_ + u0 + u) * H1_ + kk];
        }
        float* Wx = (float*)S->Wx1d;                      // 4096 floats
        for (int idx = tid; idx < F_ * U1 * 4; idx += NTHR) {
            int k2 = idx >> 7, rem = idx & 127;
            int u = rem >> 3, p = (rem >> 2) & 1, j = rem & 3;
            int gate = 2 * p + (j >> 1), kk = 2 * k2 + (j & 1);
            Wx[idx] = Wih1[(gate * H1_ + u0 + u) * F_ + kk];
        }
        float* Wa = (float*)S->W2ad;                      // 8192 floats
        for (int idx = tid; idx < H1_ * U2 * 4; idx += NTHR) {
            int k2 = idx >> 6, rem = idx & 63;
            int u = rem >> 3, p = (rem >> 2) & 1, j = rem & 3;
            int gate = 2 * p + (j >> 1), kk = 2 * k2 + (j & 1);
            Wa[idx] = Wih2[(gate * H2_ + v0 + u) * H1_ + kk];
        }
        float* Wb = (float*)S->W2bd;                      // 4096 floats
        for (int idx = tid; idx < H2_ * U2 * 4; idx += NTHR) {
            int k2 = idx >> 6, rem = idx & 63;
            int u = rem >> 3, p = (rem >> 2) & 1, j = rem & 3;
            int gate = 2 * p + (j >> 1), kk = 2 * k2 + (j & 1);
            Wb[idx] = Whh2[(gate * H2_ + v0 + u) * H2_ + kk];
        }
        if (tid < U1 * 4) {
            int j = tid >> 2, g = tid & 3;
            S->bias1[tid] = bih1[g * H1_ + u0 + j] + bhh1[g * H1_ + u0 + j];
        }
        if (tid < U2 * 4) {
            int j = tid >> 2, g = tid & 3;
            S->bias2[tid] = bih2[g * H2_ + v0 + j] + bhh2[g * H2_ + v0 + j];
        }
    }
    __syncthreads();

    // ---- thread mapping ----
    const int wN   = tid >> 5;
    const int lane = tid & 31;
    // layer 1: warp wN -> units {2wN, 2wN+1}; thread = unit u1i, rows rs & rs+16
    const int us   = lane >> 4;
    const int rs   = lane & 15;
    const int u1i  = 2 * wN + us;
    // layer 2: warp wN -> unit pair p2 = wN>>1, row half = wN&1
    const int p2   = wN >> 1;
    const int v2i  = 2 * p2 + us;
    const int r2   = (wN & 1) * 16 + rs;

    float c1A = 0.0f, c1B = 0.0f, c2 = 0.0f;   // cell states (registers)

    // iteration t: layer-1 step t (t<=T), layer-2 produces h2(t-1) (t>=2)
    for (int t = 1; t <= T_ + 1; ++t) {
        const int rslot = (t - 1) & 1;

        // ================= phase A: layer 1 =================
        if (t > 1) {
            if (tid == 0) {
                const int target = GCOL * (t - 1);
                int v;
                do {
                    asm volatile("ld.acquire.gpu.u32 %0, [%1];"
                                 : "=r"(v) : "l"(&g_cnt1[bg]) : "memory");
                } while (v < target);
            }
            __syncthreads();
        }
        // stage x_t and h1(t-1)
        if (t <= T_) {
            for (int i = tid; i < BC * F_ / 4; i += NTHR) {
                int row = i >> 4, col = i & 15;
                const float4* sx = (const float4*)(x + (size_t)(B0 + row) * T_ * F_
                                                     + (size_t)(t - 1) * F_);
                *(float4*)&S->xs[row][col * 4] = __ldg(&sx[col]);
            }
        }
        {
            const float4* s1 = (const float4*)&g_h1buf[rslot][B0][0];
            for (int i = tid; i < BC * H1_ / 4; i += NTHR) {
                int row = i >> 6, col = i & 63;
                *(float4*)&S->h1s[row][col * 4] = __ldcg(&s1[i]);
            }
        }
        __syncthreads();

        if (t <= T_) {
            const float* bb = &S->bias1[u1i * 4];
            unsigned long long aIA = pack2(bb[0], 0.f), aFA = pack2(bb[1], 0.f);
            unsigned long long aGA = pack2(bb[2], 0.f), aOA = pack2(bb[3], 0.f);
            unsigned long long aIB = pack2(bb[0], 0.f), aFB = pack2(bb[1], 0.f);
            unsigned long long aGB = pack2(bb[2], 0.f), aOB = pack2(bb[3], 0.f);

            const ulonglong2* __restrict__ Wk = &S->Wh1d[0][u1i][0];
            const ulonglong2* __restrict__ hApt = (const ulonglong2*)&S->h1s[rs][0];
            const ulonglong2* __restrict__ hBpt = (const ulonglong2*)&S->h1s[rs + 16][0];
            #pragma unroll 4
            for (int k4 = 0; k4 < H1_ / 4; ++k4) {
                ulonglong2 hA = hApt[k4];
                ulonglong2 hB = hBpt[k4];
                ulonglong2 w0 = Wk[k4 * 64 + 0];
                ulonglong2 w1 = Wk[k4 * 64 + 1];
                ulonglong2 w2 = Wk[k4 * 64 + 32];
                ulonglong2 w3 = Wk[k4 * 64 + 33];
                FMA2(aIA, hA.x, w0.x);  FMA2(aFA, hA.x, w0.y);
                FMA2(aGA, hA.x, w1.x);  FMA2(aOA, hA.x, w1.y);
                FMA2(aIA, hA.y, w2.x);  FMA2(aFA, hA.y, w2.y);
                FMA2(aGA, hA.y, w3.x);  FMA2(aOA, hA.y, w3.y);
                FMA2(aIB, hB.x, w0.x);  FMA2(aFB, hB.x, w0.y);
                FMA2(aGB, hB.x, w1.x);  FMA2(aOB, hB.x, w1.y);
                FMA2(aIB, hB.y, w2.x);  FMA2(aFB, hB.y, w2.y);
                FMA2(aGB, hB.y, w3.x);  FMA2(aOB, hB.y, w3.y);
            }
            const ulonglong2* __restrict__ Wxk = &S->Wx1d[0][u1i][0];
            const ulonglong2* __restrict__ xApt = (const ulonglong2*)&S->xs[rs][0];
            const ulonglong2* __restrict__ xBpt = (const ulonglong2*)&S->xs[rs + 16][0];
            #pragma unroll 4
            for (int k4 = 0; k4 < F_ / 4; ++k4) {
                ulonglong2 hA = xApt[k4];
                ulonglong2 hB = xBpt[k4];
                ulonglong2 w0 = Wxk[k4 * 64 + 0];
                ulonglong2 w1 = Wxk[k4 * 64 + 1];
                ulonglong2 w2 = Wxk[k4 * 64 + 32];
                ulonglong2 w3 = Wxk[k4 * 64 + 33];
                FMA2(aIA, hA.x, w0.x);  FMA2(aFA, hA.x, w0.y);
                FMA2(aGA, hA.x, w1.x);  FMA2(aOA, hA.x, w1.y);
                FMA2(aIA, hA.y, w2.x);  FMA2(aFA, hA.y, w2.y);
                FMA2(aGA, hA.y, w3.x);  FMA2(aOA, hA.y, w3.y);
                FMA2(aIB, hB.x, w0.x);  FMA2(aFB, hB.x, w0.y);
                FMA2(aGB, hB.x, w1.x);  FMA2(aOB, hB.x, w1.y);
                FMA2(aIB, hB.y, w2.x);  FMA2(aFB, hB.y, w2.y);
                FMA2(aGB, hB.y, w3.x);  FMA2(aOB, hB.y, w3.y);
            }

            float2 pI = unpack2(aIA), pF = unpack2(aFA), pG = unpack2(aGA), pO = unpack2(aOA);
            float iA = sigf(pI.x + pI.y), fA = sigf(pF.x + pF.y);
            float gA = tanh_f(pG.x + pG.y), oA = sigf(pO.x + pO.y);
            c1A = fA * c1A + iA * gA;
            g_h1buf[t & 1][B0 + rs][u0 + u1i] = oA * tanh_f(c1A);

            pI = unpack2(aIB); pF = unpack2(aFB); pG = unpack2(aGB); pO = unpack2(aOB);
            float iB = sigf(pI.x + pI.y), fB = sigf(pF.x + pF.y);
            float gB = tanh_f(pG.x + pG.y), oB = sigf(pO.x + pO.y);
            c1B = fB * c1B + iB * gB;
            g_h1buf[t & 1][B0 + rs + 16][u0 + u1i] = oB * tanh_f(c1B);

            __syncthreads();
            if (tid == 0) {
                asm volatile("red.release.gpu.global.add.u32 [%0], %1;"
                             :: "l"(&g_cnt1[bg]), "r"(1) : "memory");
            }
        }

        // ================= phase B: layer 2 (produces h2(t-1)) =================
        if (t >= 2) {
            if (tid == 0) {
                const int target = GCOL * (t - 1);
                int v;
                do {
                    asm volatile("ld.acquire.gpu.u32 %0, [%1];"
                                 : "=r"(v) : "l"(&g_cnt2[bg]) : "memory");
                } while (v < target);
            }
            __syncthreads();
            {   // stage h2(t-2)
                const float4* s2 = (const float4*)&g_h2buf[rslot][B0][0];
                for (int i = tid; i < BC * H2_ / 4; i += NTHR) {
                    int row = i >> 5, col = i & 31;
                    *(float4*)&S->h2s[row][col * 4] = __ldcg(&s2[i]);
                }
            }
            __syncthreads();

            const float* bb2 = &S->bias2[v2i * 4];
            unsigned long long aI = pack2(bb2[0], 0.f), aF = pack2(bb2[1], 0.f);
            unsigned long long aG = pack2(bb2[2], 0.f), aO = pack2(bb2[3], 0.f);

            const ulonglong2* __restrict__ Wa = &S->W2ad[0][v2i][0];
            const ulonglong2* __restrict__ hpt = (const ulonglong2*)&S->h1s[r2][0];
            #pragma unroll 4
            for (int k4 = 0; k4 < H1_ / 4; ++k4) {
                ulonglong2 h = hpt[k4];
                ulonglong2 w0 = Wa[k4 * 32 + 0];
                ulonglong2 w1 = Wa[k4 * 32 + 1];
                ulonglong2 w2 = Wa[k4 * 32 + 16];
                ulonglong2 w3 = Wa[k4 * 32 + 17];
                FMA2(aI, h.x, w0.x);  FMA2(aF, h.x, w0.y);
                FMA2(aG, h.x, w1.x);  FMA2(aO, h.x, w1.y);
                FMA2(aI, h.y, w2.x);  FMA2(aF, h.y, w2.y);
                FMA2(aG, h.y, w3.x);  FMA2(aO, h.y, w3.y);
            }
            const ulonglong2* __restrict__ Wb = &S->W2bd[0][v2i][0];
            const ulonglong2* __restrict__ cpt = (const ulonglong2*)&S->h2s[r2][0];
            #pragma unroll 4
            for (int k4 = 0; k4 < H2_ / 4; ++k4) {
                ulonglong2 h = cpt[k4];
                ulonglong2 w0 = Wb[k4 * 32 + 0];
                ulonglong2 w1 = Wb[k4 * 32 + 1];
                ulonglong2 w2 = Wb[k4 * 32 + 16];
                ulonglong2 w3 = Wb[k4 * 32 + 17];
                FMA2(aI, h.x, w0.x);  FMA2(aF, h.x, w0.y);
                FMA2(aG, h.x, w1.x);  FMA2(aO, h.x, w1.y);
                FMA2(aI, h.y, w2.x);  FMA2(aF, h.y, w2.y);
                FMA2(aG, h.y, w3.x);  FMA2(aO, h.y, w3.y);
            }
            float2 pI = unpack2(aI), pF = unpack2(aF), pG = unpack2(aG), pO = unpack2(aO);
            float i2 = sigf(pI.x + pI.y), f2 = sigf(pF.x + pF.y);
            float g2 = tanh_f(pG.x + pG.y), o2 = sigf(pO.x + pO.y);
            c2 = f2 * c2 + i2 * g2;
            g_h2buf[t & 1][B0 + r2][v0 + v2i] = o2 * tanh_f(c2);

            __syncthreads();
            if (tid == 0 && t <= T_ + 1) {
                asm volatile("red.release.gpu.global.add.u32 [%0], %1;"
                             :: "l"(&g_cnt2[bg]), "r"(1) : "memory");
            }
        } else {
            // t == 1: publish h2(0) = 0 into slot 1
            g_h2buf[1][B0 + r2][v0 + v2i] = 0.0f;
            __syncthreads();
            if (tid == 0) {
                asm volatile("red.release.gpu.global.add.u32 [%0], %1;"
                             :: "l"(&g_cnt2[bg]), "r"(1) : "memory");
            }
        }
    }
}

// ---- MLP head: out = relu(hT2 @ W1^T + b1) @ W2^T + b2 ----
__global__ void classifier_kernel(const float* __restrict__ W1, const float* __restrict__ b1,
                                  const float* __restrict__ W2, const float* __restrict__ b2,
                                  float* __restrict__ out)
{
    __shared__ float hrow[H2_];
    __shared__ float z[DMLP_];
    const int row = blockIdx.x;
    const int tid = threadIdx.x;   // 128

    hrow[tid] = g_h2buf[(T_ + 1) & 1][row][tid];   // h2(T) lives in slot 1
    __syncthreads();

    float acc = b1[tid];
    #pragma unroll 8
    for (int k = 0; k < H2_; ++k) acc += hrow[k] * W1[tid * H2_ + k];
    z[tid] = fmaxf(acc, 0.0f);
    __syncthreads();

    if (tid < NCLS_) {
        float o = b2[tid];
        #pragma unroll 8
        for (int j = 0; j < DMLP_; ++j) o += z[j] * W2[tid * DMLP_ + j];
        out[row * NCLS_ + tid] = o;
    }
}

extern "C" void kernel_launch(void* const* d_in, const int* in_sizes, int n_in,
                              void* d_out, int out_size)
{
    (void)in_sizes; (void)n_in; (void)out_size;
    const float* x    = (const float*)d_in[0];
    const float* Wih1 = (const float*)d_in[1];
    const float* Whh1 = (const float*)d_in[2];
    const float* bih1 = (const float*)d_in[3];
    const float* bhh1 = (const float*)d_in[4];
    const float* Wih2 = (const float*)d_in[5];
    const float* Whh2 = (const float*)d_in[6];
    const float* bih2 = (const float*)d_in[7];
    const float* bhh2 = (const float*)d_in[8];
    const float* W1   = (const float*)d_in[9];
    const float* b1   = (const float*)d_in[10];
    const float* W2   = (const float*)d_in[11];
    const float* b2   = (const float*)d_in[12];
    float* out = (float*)d_out;

    cudaFuncSetAttribute(lstm_persistent,
                         cudaFuncAttributeMaxDynamicSharedMemorySize, (int)SMEM_BYTES);

    lstm_init_kernel<<<256, 256>>>();
    lstm_persistent<<<GB * GCOL, NTHR, SMEM_BYTES>>>(
        x, Wih1, Whh1, bih1, bhh1, Wih2, Whh2, bih2, bhh2);
    classifier_kernel<<<B_, DMLP_>>>(W1, b1, W2, b2, out);
}